// round 3
// baseline (speedup 1.0000x reference)
#include <cuda_runtime.h>
#include <math.h>

#define NN 100000
#define EE 1600000
#define DD 64
#define TAU 0.5f
#define ITERS 10

#define CB 148            // cooperative grid blocks (<= SM count)
#define CT 1024           // cooperative block threads
#define NP1 (NN + 1)
#define NCHUNK ((NP1 + CT - 1) / CT)   // 98 chunks per array

// ---------------- scratch (no cudaMalloc allowed) ----------------
__device__ float g_X[NN * DD];      // layer1 output
__device__ float g_X2[NN * DD];     // layer2 output
__device__ float g_v[NN];           // power vector
__device__ float g_norms[ITERS];
__device__ int   g_rsA[NP1];        // CSR row starts for A (also hist scratch)
__device__ int   g_rsL[NP1];
__device__ int   g_fillA[NN];
__device__ int   g_fillL[NN];
__device__ int2  g_eA[EE];          // {col, val_bits} CSR-ordered
__device__ int2  g_eL[EE];
__device__ int   g_bsumA[NCHUNK];
__device__ int   g_bsumL[NCHUNK];
__device__ unsigned g_count;            // barrier arrivals
__device__ volatile unsigned g_sense;   // barrier release (monotonic)

// ---------------------------------------------------------------------------
__device__ __forceinline__ void grid_sync(unsigned* sense) {
    __syncthreads();
    if (threadIdx.x == 0) {
        unsigned s = *sense + 1;
        *sense = s;
        __threadfence();
        unsigned prev = atomicAdd(&g_count, 1u);
        if (prev == gridDim.x - 1) {
            g_count = 0;
            __threadfence();
            g_sense = s;
        } else {
            while (g_sense != s) __nanosleep(32);
            __threadfence();
        }
    }
    __syncthreads();
}

// ---------------------------------------------------------------------------
// One cooperative kernel: zero -> hist(A,L) -> 3-stage scan(A,L) -> scatter(A,L)
__global__ __launch_bounds__(CT, 1)
void csr_build_kernel(const int* __restrict__ Arow, const int* __restrict__ Acol,
                      const float* __restrict__ Aval,
                      const int* __restrict__ Lrow, const int* __restrict__ Lcol,
                      const float* __restrict__ Lval, int E) {
    __shared__ unsigned sense;
    __shared__ int sm[CT];
    const int tid = threadIdx.x;
    const int gtid = blockIdx.x * CT + tid;
    const int gs = gridDim.x * CT;
    if (tid == 0) sense = g_sense;

    // phase 0: zero counters + norms
    for (int i = gtid; i < NP1; i += gs) { __stcg(&g_rsA[i], 0); __stcg(&g_rsL[i], 0); }
    if (gtid < ITERS) __stcg(&g_norms[gtid], 0.f);
    grid_sync(&sense);

    // phase 1: histogram (counts at row+1)
    for (int e = gtid; e < E; e += gs) {
        atomicAdd(&g_rsA[__ldg(Arow + e) + 1], 1);
        atomicAdd(&g_rsL[__ldg(Lrow + e) + 1], 1);
    }
    grid_sync(&sense);

    // phase 2a: per-chunk inclusive scan (both arrays)
    for (int chunk = blockIdx.x; chunk < 2 * NCHUNK; chunk += gridDim.x) {
        int* arr = (chunk < NCHUNK) ? g_rsA : g_rsL;
        int* bs  = (chunk < NCHUNK) ? g_bsumA : g_bsumL;
        int c = (chunk < NCHUNK) ? chunk : chunk - NCHUNK;
        int idx = c * CT + tid;
        int x = (idx < NP1) ? __ldcg(&arr[idx]) : 0;
        sm[tid] = x;
        __syncthreads();
#pragma unroll
        for (int off = 1; off < CT; off <<= 1) {
            int t = (tid >= off) ? sm[tid - off] : 0;
            __syncthreads();
            sm[tid] += t;
            __syncthreads();
        }
        if (idx < NP1) __stcg(&arr[idx], sm[tid]);
        if (tid == CT - 1) __stcg(&bs[c], sm[tid]);
        __syncthreads();
    }
    grid_sync(&sense);

    // phase 2b: scan chunk sums (block 0 -> A, block 1 -> L)
    if (blockIdx.x < 2) {
        int* bs = blockIdx.x ? g_bsumL : g_bsumA;
        int x = (tid < NCHUNK) ? __ldcg(&bs[tid]) : 0;
        sm[tid] = x;
        __syncthreads();
#pragma unroll
        for (int off = 1; off < CT; off <<= 1) {
            int t = (tid >= off) ? sm[tid - off] : 0;
            __syncthreads();
            sm[tid] += t;
            __syncthreads();
        }
        if (tid < NCHUNK) __stcg(&bs[tid], sm[tid]);
    }
    grid_sync(&sense);

    // phase 2c: add chunk offsets, init fill cursors
    for (int i = gtid; i < NP1; i += gs) {
        int chunk = i / CT;
        int a = __ldcg(&g_rsA[i]) + (chunk ? __ldcg(&g_bsumA[chunk - 1]) : 0);
        int l = __ldcg(&g_rsL[i]) + (chunk ? __ldcg(&g_bsumL[chunk - 1]) : 0);
        __stcg(&g_rsA[i], a);
        __stcg(&g_rsL[i], l);
        if (i < NN) { __stcg(&g_fillA[i], a); __stcg(&g_fillL[i], l); }
    }
    grid_sync(&sense);

    // phase 3: scatter edges into CSR order
    for (int e = gtid; e < E; e += gs) {
        int ra = __ldg(Arow + e);
        int pa = atomicAdd(&g_fillA[ra], 1);
        g_eA[pa] = make_int2(__ldg(Acol + e), __float_as_int(__ldg(Aval + e)));
        int rl = __ldg(Lrow + e);
        int pl = atomicAdd(&g_fillL[rl], 1);
        g_eL[pl] = make_int2(__ldg(Lcol + e), __float_as_int(__ldg(Lval + e)));
    }
}

// ---------------------------------------------------------------------------
// Fused SpMM + residual Linear (+ optional score): 16 lanes per row.
// AX row built in registers (float4 per lane), exchanged via smem,
// 64x64 matmul with transposed W in smem, residual + relu, optional Ws dot.
__global__ __launch_bounds__(512)
void layer_kernel(const float* __restrict__ Xin, float* __restrict__ Xout,
                  const float* __restrict__ W, const float* __restrict__ Ws,
                  float* __restrict__ vout, int layer2) {
    __shared__ float  Wt[DD * DD];        // Wt[k*64 + d] = W[d][k]
    __shared__ float4 rowbuf[32][16];     // 32 rows per block
    __shared__ float4 WsS[16];
    const int tid = threadIdx.x;

    for (int i = tid; i < DD * DD; i += 512) {
        int k = i >> 6, d = i & 63;
        Wt[k * DD + d] = __ldg(&W[d * DD + k]);
    }
    if (tid < 16) WsS[tid] = __ldg(&((const float4*)Ws)[tid]);
    __syncthreads();

    // grid covers exactly NN*16 threads (NN*16 % 512 == 0)
    const int gt = blockIdx.x * 512 + tid;
    const int r = gt >> 4;
    const int c = gt & 15;

    // SpMM: acc = sum_e val * Xin[col][4c..4c+3]
    int s = __ldg(&g_rsA[r]);
    int e = __ldg(&g_rsA[r + 1]);
    float4 acc = make_float4(0.f, 0.f, 0.f, 0.f);
    int i = s;
    for (; i + 1 < e; i += 2) {
        int2 p0 = __ldg(&g_eA[i]);
        int2 p1 = __ldg(&g_eA[i + 1]);
        float v0 = __int_as_float(p0.y), v1 = __int_as_float(p1.y);
        float4 a = __ldg(((const float4*)(Xin + (size_t)p0.x * DD)) + c);
        float4 b = __ldg(((const float4*)(Xin + (size_t)p1.x * DD)) + c);
        acc.x += v0 * a.x + v1 * b.x;
        acc.y += v0 * a.y + v1 * b.y;
        acc.z += v0 * a.z + v1 * b.z;
        acc.w += v0 * a.w + v1 * b.w;
    }
    if (i < e) {
        int2 p = __ldg(&g_eA[i]);
        float v = __int_as_float(p.y);
        float4 a = __ldg(((const float4*)(Xin + (size_t)p.x * DD)) + c);
        acc.x += v * a.x; acc.y += v * a.y; acc.z += v * a.z; acc.w += v * a.w;
    }

    // exchange AX row across the 16 lanes
    const int slot = tid >> 4;
    rowbuf[slot][c] = acc;
    __syncwarp();

    // Linear: out[d] = sum_k AXrow[k] * W[d][k], lane c owns d = 4c..4c+3
    float4 o = make_float4(0.f, 0.f, 0.f, 0.f);
#pragma unroll
    for (int k4 = 0; k4 < 16; k4++) {
        float4 xr = rowbuf[slot][k4];                    // smem broadcast
        const float* xk = (const float*)&xr;
#pragma unroll
        for (int j = 0; j < 4; j++) {
            int k = k4 * 4 + j;
            float4 w = ((const float4*)(Wt + k * DD))[c]; // conflict-free
            float x = xk[j];
            o.x += x * w.x; o.y += x * w.y; o.z += x * w.z; o.w += x * w.w;
        }
    }

    float4 xi = __ldg(((const float4*)(Xin + (size_t)r * DD)) + c);
    float4 res;
    res.x = xi.x + fmaxf(o.x, 0.f);
    res.y = xi.y + fmaxf(o.y, 0.f);
    res.z = xi.z + fmaxf(o.z, 0.f);
    res.w = xi.w + fmaxf(o.w, 0.f);
    ((float4*)(Xout + (size_t)r * DD))[c] = res;

    if (layer2) {
        float4 ws = WsS[c];
        float pv = res.x * ws.x + res.y * ws.y + res.z * ws.z + res.w * ws.w;
        pv += __shfl_xor_sync(0xFFFFFFFFu, pv, 8, 16);
        pv += __shfl_xor_sync(0xFFFFFFFFu, pv, 4, 16);
        pv += __shfl_xor_sync(0xFFFFFFFFu, pv, 2, 16);
        pv += __shfl_xor_sync(0xFFFFFFFFu, pv, 1, 16);
        if (c == 0) vout[r] = pv;
    }
}

// ---------------------------------------------------------------------------
// All 10 power iterations, CSR-L row-parallel (no atomics on tmp), 2 barriers/iter.
__global__ __launch_bounds__(CT, 1)
void power_kernel(float* __restrict__ out) {
    __shared__ unsigned sense;
    __shared__ float wsum[CT / 32];
    const int tid = threadIdx.x;
    const int gtid = blockIdx.x * CT + tid;
    const int lane = tid & 31, wid = tid >> 5;
    if (tid == 0) sense = g_sense;
    __syncthreads();

    int s = 0, e = 0;
    if (gtid < NN) {
        s = __ldg(&g_rsL[gtid]);
        e = __ldg(&g_rsL[gtid + 1]);
    }

    for (int it = 0; it < ITERS; it++) {
        // SpMV row: acc = sum val * v[col]   (edge data L1-resident after iter 0)
        float acc = 0.f;
        int i = s;
        for (; i + 1 < e; i += 2) {
            int2 p0 = __ldg(&g_eL[i]);
            int2 p1 = __ldg(&g_eL[i + 1]);
            float v0 = __ldcg(&g_v[p0.x]);
            float v1 = __ldcg(&g_v[p1.x]);
            acc += __int_as_float(p0.y) * v0 + __int_as_float(p1.y) * v1;
        }
        if (i < e) {
            int2 p = __ldg(&g_eL[i]);
            acc += __int_as_float(p.y) * __ldcg(&g_v[p.x]);
        }

        // shrink + local norm
        float y = 0.f, sq = 0.f;
        if (gtid < NN) {
            float sg = (acc > 0.f) ? 1.f : ((acc < 0.f) ? -1.f : 0.f);
            y = acc - TAU * sg;
            sq = y * y;
        }
#pragma unroll
        for (int off = 16; off > 0; off >>= 1)
            sq += __shfl_down_sync(0xFFFFFFFFu, sq, off);
        if (lane == 0) wsum[wid] = sq;
        __syncthreads();
        if (wid == 0) {
            sq = wsum[lane];
#pragma unroll
            for (int off = 16; off > 0; off >>= 1)
                sq += __shfl_down_sync(0xFFFFFFFFu, sq, off);
            if (lane == 0) atomicAdd(&g_norms[it], sq);
        }
        grid_sync(&sense);     // norm complete; prior v reads complete

        float inv = 1.f / fmaxf(sqrtf(__ldcg(&g_norms[it])), 1e-12f);
        if (gtid < NN) {
            float r = y * inv;
            if (it == ITERS - 1) out[gtid] = r;
            else __stcg(&g_v[gtid], r);
        }
        grid_sync(&sense);     // new v visible before next SpMV
    }
}

// ---------------------------------------------------------------------------
extern "C" void kernel_launch(void* const* d_in, const int* in_sizes, int n_in,
                              void* d_out, int out_size) {
    const int*   A_row = (const int*)d_in[0];
    const int*   A_col = (const int*)d_in[1];
    const float* A_val = (const float*)d_in[2];
    const int*   L_row = (const int*)d_in[3];
    const int*   L_col = (const int*)d_in[4];
    const float* L_val = (const float*)d_in[5];
    const float* embed = (const float*)d_in[6];
    const float* W1    = (const float*)d_in[7];
    const float* W2    = (const float*)d_in[8];
    const float* Ws    = (const float*)d_in[9];
    const int E = in_sizes[0];
    float* out = (float*)d_out;

    float *X, *X2, *v;
    cudaGetSymbolAddress((void**)&X,  g_X);
    cudaGetSymbolAddress((void**)&X2, g_X2);
    cudaGetSymbolAddress((void**)&v,  g_v);

    // 1) CSR build for A and L (one cooperative launch)
    csr_build_kernel<<<CB, CT>>>(A_row, A_col, A_val, L_row, L_col, L_val, E);

    // 2-3) fused GNN layers (grid covers exactly NN*16 threads)
    const int LB = (NN * 16) / 512;   // 3125
    layer_kernel<<<LB, 512>>>(embed, X,  W1, Ws, v, 0);
    layer_kernel<<<LB, 512>>>(X,     X2, W2, Ws, v, 1);

    // 4) power iterations (one cooperative launch)
    power_kernel<<<CB, CT>>>(out);
}

// round 4
// speedup vs baseline: 1.0637x; 1.0637x over previous
#include <cuda_runtime.h>
#include <math.h>

#define NN 100000
#define EE 1600000
#define DD 64
#define TAU 0.5f
#define ITERS 10

#define CB 296             // cooperative grid blocks (2 per SM)
#define CT 512             // cooperative block threads
#define NP1 (NN + 1)
#define NCHUNK ((NP1 + CT - 1) / CT)      // 196
#define RPB ((NN + CB - 1) / CB)          // 338 rows per power block

// ---------------- scratch (no cudaMalloc allowed) ----------------
__device__ float g_X[NN * DD];      // layer1 output
__device__ float g_X2[NN * DD];     // layer2 output
__device__ float g_ya[NN];          // power ping buffer (scores written here)
__device__ float g_yb[NN];          // power pong buffer
__device__ float g_norms[ITERS];
__device__ int   g_rsA[NP1];
__device__ int   g_rsL[NP1];
__device__ int   g_fillA[NN];
__device__ int   g_fillL[NN];
__device__ int2  g_eA[EE];          // {col, val_bits} CSR-ordered
__device__ int2  g_eL[EE];
__device__ int   g_bsumA[NCHUNK];
__device__ int   g_bsumL[NCHUNK];
__device__ unsigned g_count;
__device__ volatile unsigned g_sense;

// ---------------------------------------------------------------------------
__device__ __forceinline__ void grid_sync(unsigned* sense) {
    __syncthreads();
    if (threadIdx.x == 0) {
        unsigned s = *sense + 1;
        *sense = s;
        __threadfence();
        unsigned prev = atomicAdd(&g_count, 1u);
        if (prev == gridDim.x - 1) {
            g_count = 0;
            __threadfence();
            g_sense = s;
        } else {
            while (g_sense != s) __nanosleep(32);
            __threadfence();
        }
    }
    __syncthreads();
}

// ---------------------------------------------------------------------------
// One cooperative kernel: zero -> hist(A,L) -> 3-stage scan -> scatter(A,L)
__global__ __launch_bounds__(CT, 2)
void csr_build_kernel(const int* __restrict__ Arow, const int* __restrict__ Acol,
                      const float* __restrict__ Aval,
                      const int* __restrict__ Lrow, const int* __restrict__ Lcol,
                      const float* __restrict__ Lval, int E) {
    __shared__ unsigned sense;
    __shared__ int sm[CT];
    const int tid = threadIdx.x;
    const int gtid = blockIdx.x * CT + tid;
    const int gs = gridDim.x * CT;
    if (tid == 0) sense = g_sense;

    for (int i = gtid; i < NP1; i += gs) { __stcg(&g_rsA[i], 0); __stcg(&g_rsL[i], 0); }
    if (gtid < ITERS) __stcg(&g_norms[gtid], 0.f);
    grid_sync(&sense);

    for (int e = gtid; e < E; e += gs) {
        atomicAdd(&g_rsA[__ldg(Arow + e) + 1], 1);
        atomicAdd(&g_rsL[__ldg(Lrow + e) + 1], 1);
    }
    grid_sync(&sense);

    // per-chunk inclusive scan (both arrays)
    for (int chunk = blockIdx.x; chunk < 2 * NCHUNK; chunk += gridDim.x) {
        int* arr = (chunk < NCHUNK) ? g_rsA : g_rsL;
        int* bs  = (chunk < NCHUNK) ? g_bsumA : g_bsumL;
        int c = (chunk < NCHUNK) ? chunk : chunk - NCHUNK;
        int idx = c * CT + tid;
        int x = (idx < NP1) ? __ldcg(&arr[idx]) : 0;
        sm[tid] = x;
        __syncthreads();
#pragma unroll
        for (int off = 1; off < CT; off <<= 1) {
            int t = (tid >= off) ? sm[tid - off] : 0;
            __syncthreads();
            sm[tid] += t;
            __syncthreads();
        }
        if (idx < NP1) __stcg(&arr[idx], sm[tid]);
        if (tid == CT - 1) __stcg(&bs[c], sm[tid]);
        __syncthreads();
    }
    grid_sync(&sense);

    // scan chunk sums (block 0 -> A, block 1 -> L)
    if (blockIdx.x < 2) {
        int* bs = blockIdx.x ? g_bsumL : g_bsumA;
        int x = (tid < NCHUNK) ? __ldcg(&bs[tid]) : 0;
        sm[tid] = x;
        __syncthreads();
#pragma unroll
        for (int off = 1; off < CT; off <<= 1) {
            int t = (tid >= off) ? sm[tid - off] : 0;
            __syncthreads();
            sm[tid] += t;
            __syncthreads();
        }
        if (tid < NCHUNK) __stcg(&bs[tid], sm[tid]);
    }
    grid_sync(&sense);

    // add chunk offsets, init fill cursors
    for (int i = gtid; i < NP1; i += gs) {
        int chunk = i / CT;
        int a = __ldcg(&g_rsA[i]) + (chunk ? __ldcg(&g_bsumA[chunk - 1]) : 0);
        int l = __ldcg(&g_rsL[i]) + (chunk ? __ldcg(&g_bsumL[chunk - 1]) : 0);
        __stcg(&g_rsA[i], a);
        __stcg(&g_rsL[i], l);
        if (i < NN) { __stcg(&g_fillA[i], a); __stcg(&g_fillL[i], l); }
    }
    grid_sync(&sense);

    // scatter edges into CSR order
    for (int e = gtid; e < E; e += gs) {
        int ra = __ldg(Arow + e);
        int pa = atomicAdd(&g_fillA[ra], 1);
        g_eA[pa] = make_int2(__ldg(Acol + e), __float_as_int(__ldg(Aval + e)));
        int rl = __ldg(Lrow + e);
        int pl = atomicAdd(&g_fillL[rl], 1);
        g_eL[pl] = make_int2(__ldg(Lcol + e), __float_as_int(__ldg(Lval + e)));
    }
}

// ---------------------------------------------------------------------------
// Fused SpMM + residual Linear (+ optional score): 16 lanes per row.
__global__ __launch_bounds__(512, 2)
void layer_kernel(const float* __restrict__ Xin, float* __restrict__ Xout,
                  const float* __restrict__ W, const float* __restrict__ Ws,
                  float* __restrict__ vout, int layer2) {
    __shared__ float  Wt[DD * DD];        // Wt[k*64 + d] = W[d][k]
    __shared__ float4 rowbuf[32][16];
    __shared__ float4 WsS[16];
    const int tid = threadIdx.x;

    for (int i = tid; i < DD * DD; i += 512) {
        int k = i >> 6, d = i & 63;
        Wt[k * DD + d] = __ldg(&W[d * DD + k]);
    }
    if (tid < 16) WsS[tid] = __ldg(&((const float4*)Ws)[tid]);
    __syncthreads();

    const int gt = blockIdx.x * 512 + tid;
    const int r = gt >> 4;
    const int c = gt & 15;

    int s = __ldg(&g_rsA[r]);
    int e = __ldg(&g_rsA[r + 1]);
    float4 acc = make_float4(0.f, 0.f, 0.f, 0.f);
    int i = s;
    if (i < e && (i & 1)) {           // align to even for int4 pair loads
        int2 p = __ldg(&g_eA[i]);
        float v = __int_as_float(p.y);
        float4 a = __ldg(((const float4*)(Xin + (size_t)p.x * DD)) + c);
        acc.x += v * a.x; acc.y += v * a.y; acc.z += v * a.z; acc.w += v * a.w;
        i++;
    }
    for (; i + 3 < e; i += 4) {       // 4-edge MLP, 2x LDG.128 edge loads
        int4 q0 = __ldg((const int4*)(g_eA + i));
        int4 q1 = __ldg((const int4*)(g_eA + i + 2));
        float4 a = __ldg(((const float4*)(Xin + (size_t)q0.x * DD)) + c);
        float4 b = __ldg(((const float4*)(Xin + (size_t)q0.z * DD)) + c);
        float4 d2 = __ldg(((const float4*)(Xin + (size_t)q1.x * DD)) + c);
        float4 f = __ldg(((const float4*)(Xin + (size_t)q1.z * DD)) + c);
        float v0 = __int_as_float(q0.y), v1 = __int_as_float(q0.w);
        float v2 = __int_as_float(q1.y), v3 = __int_as_float(q1.w);
        acc.x += v0 * a.x + v1 * b.x + v2 * d2.x + v3 * f.x;
        acc.y += v0 * a.y + v1 * b.y + v2 * d2.y + v3 * f.y;
        acc.z += v0 * a.z + v1 * b.z + v2 * d2.z + v3 * f.z;
        acc.w += v0 * a.w + v1 * b.w + v2 * d2.w + v3 * f.w;
    }
    for (; i < e; i++) {
        int2 p = __ldg(&g_eA[i]);
        float v = __int_as_float(p.y);
        float4 a = __ldg(((const float4*)(Xin + (size_t)p.x * DD)) + c);
        acc.x += v * a.x; acc.y += v * a.y; acc.z += v * a.z; acc.w += v * a.w;
    }

    const int slot = tid >> 4;
    rowbuf[slot][c] = acc;
    __syncwarp();

    float4 o = make_float4(0.f, 0.f, 0.f, 0.f);
#pragma unroll
    for (int k4 = 0; k4 < 16; k4++) {
        float4 xr = rowbuf[slot][k4];
        const float* xk = (const float*)&xr;
#pragma unroll
        for (int j = 0; j < 4; j++) {
            int k = k4 * 4 + j;
            float4 w = ((const float4*)(Wt + k * DD))[c];
            float x = xk[j];
            o.x += x * w.x; o.y += x * w.y; o.z += x * w.z; o.w += x * w.w;
        }
    }

    float4 xi = __ldg(((const float4*)(Xin + (size_t)r * DD)) + c);
    float4 res;
    res.x = xi.x + fmaxf(o.x, 0.f);
    res.y = xi.y + fmaxf(o.y, 0.f);
    res.z = xi.z + fmaxf(o.z, 0.f);
    res.w = xi.w + fmaxf(o.w, 0.f);
    ((float4*)(Xout + (size_t)r * DD))[c] = res;

    if (layer2) {
        float4 ws = WsS[c];
        float pv = res.x * ws.x + res.y * ws.y + res.z * ws.z + res.w * ws.w;
        pv += __shfl_xor_sync(0xFFFFFFFFu, pv, 8, 16);
        pv += __shfl_xor_sync(0xFFFFFFFFu, pv, 4, 16);
        pv += __shfl_xor_sync(0xFFFFFFFFu, pv, 2, 16);
        pv += __shfl_xor_sync(0xFFFFFFFFu, pv, 1, 16);
        if (c == 0) vout[r] = pv;
    }
}

// ---------------------------------------------------------------------------
// Power iterations: lazy normalization (1 barrier/iter), ping-pong buffers,
// block-balanced rows (all 148 SMs loaded), 4-edge MLP SpMV.
__global__ __launch_bounds__(CT, 2)
void power_kernel(float* __restrict__ out) {
    __shared__ unsigned sense;
    __shared__ float wsum[CT / 32];
    const int tid = threadIdx.x;
    const int lane = tid & 31, wid = tid >> 5;
    if (tid == 0) sense = g_sense;
    __syncthreads();

    const int r = blockIdx.x * RPB + tid;      // threads RPB..CT-1 idle
    const bool active = (tid < RPB) && (r < NN);
    int s = 0, e = 0;
    if (active) {
        s = __ldg(&g_rsL[r]);
        e = __ldg(&g_rsL[r + 1]);
    }

    float y = 0.f;
    for (int it = 0; it < ITERS; it++) {
        float alpha = 1.f;
        if (it > 0)
            alpha = 1.f / fmaxf(sqrtf(__ldcg(&g_norms[it - 1])), 1e-12f);
        const float* src = (it & 1) ? g_yb : g_ya;
        float* dst = (it & 1) ? g_ya : g_yb;

        float acc = 0.f;
        if (active) {
            int i = s;
            if (i < e && (i & 1)) {
                int2 p = __ldg(&g_eL[i]);
                acc += __int_as_float(p.y) * __ldcg(&src[p.x]);
                i++;
            }
            for (; i + 3 < e; i += 4) {
                int4 q0 = __ldg((const int4*)(g_eL + i));
                int4 q1 = __ldg((const int4*)(g_eL + i + 2));
                float v0 = __ldcg(&src[q0.x]);
                float v1 = __ldcg(&src[q0.z]);
                float v2 = __ldcg(&src[q1.x]);
                float v3 = __ldcg(&src[q1.z]);
                acc += __int_as_float(q0.y) * v0 + __int_as_float(q0.w) * v1;
                acc += __int_as_float(q1.y) * v2 + __int_as_float(q1.w) * v3;
            }
            for (; i < e; i++) {
                int2 p = __ldg(&g_eL[i]);
                acc += __int_as_float(p.y) * __ldcg(&src[p.x]);
            }
        }

        // z = alpha * acc; shrink; store unnormalized y; accumulate norm
        float sq = 0.f;
        if (active) {
            float z = alpha * acc;
            float sg = (z > 0.f) ? 1.f : ((z < 0.f) ? -1.f : 0.f);
            y = z - TAU * sg;
            sq = y * y;
            __stcg(&dst[r], y);
        }
#pragma unroll
        for (int off = 16; off > 0; off >>= 1)
            sq += __shfl_down_sync(0xFFFFFFFFu, sq, off);
        if (lane == 0) wsum[wid] = sq;
        __syncthreads();
        if (wid == 0) {
            sq = wsum[lane & 15];
            if (lane >= (CT >> 5)) sq = 0.f;
#pragma unroll
            for (int off = 8; off > 0; off >>= 1)
                sq += __shfl_down_sync(0xFFFFFFFFu, sq, off);
            if (lane == 0) atomicAdd(&g_norms[it], sq);
        }
        grid_sync(&sense);   // y writes + norm complete before next iter
    }

    if (active) {
        float inv = 1.f / fmaxf(sqrtf(__ldcg(&g_norms[ITERS - 1])), 1e-12f);
        out[r] = y * inv;    // y still in register
    }
}

// ---------------------------------------------------------------------------
extern "C" void kernel_launch(void* const* d_in, const int* in_sizes, int n_in,
                              void* d_out, int out_size) {
    const int*   A_row = (const int*)d_in[0];
    const int*   A_col = (const int*)d_in[1];
    const float* A_val = (const float*)d_in[2];
    const int*   L_row = (const int*)d_in[3];
    const int*   L_col = (const int*)d_in[4];
    const float* L_val = (const float*)d_in[5];
    const float* embed = (const float*)d_in[6];
    const float* W1    = (const float*)d_in[7];
    const float* W2    = (const float*)d_in[8];
    const float* Ws    = (const float*)d_in[9];
    const int E = in_sizes[0];
    float* out = (float*)d_out;

    float *X, *X2, *ya;
    cudaGetSymbolAddress((void**)&X,  g_X);
    cudaGetSymbolAddress((void**)&X2, g_X2);
    cudaGetSymbolAddress((void**)&ya, g_ya);

    csr_build_kernel<<<CB, CT>>>(A_row, A_col, A_val, L_row, L_col, L_val, E);

    const int LB = (NN * 16) / 512;   // 3125
    layer_kernel<<<LB, 512>>>(embed, X,  W1, Ws, ya, 0);
    layer_kernel<<<LB, 512>>>(X,     X2, W2, Ws, ya, 1);  // scores -> g_ya

    power_kernel<<<CB, CT>>>(out);
}

// round 5
// speedup vs baseline: 1.1034x; 1.0374x over previous
#include <cuda_runtime.h>
#include <math.h>

#define NN 100000
#define EE 1600000
#define DD 64
#define TAU 0.5f
#define ITERS 10

#define CB 296                         // cooperative blocks (2/SM)
#define CSRT 512                       // csr kernel threads
#define PWT 384                        // power kernel threads
#define NP1 (NN + 1)
#define NCHUNK ((NP1 + CSRT - 1) / CSRT)   // 196
#define RPB ((NN + CB - 1) / CB)           // 338 rows per power block
#define ECAP 7936                          // smem edge cache per block (62KB)

// ---------------- scratch (no cudaMalloc allowed) ----------------
__device__ float g_X[NN * DD];
__device__ float g_X2[NN * DD];
__device__ float g_ya[NN];
__device__ float g_yb[NN];
__device__ float g_norms[ITERS];
__device__ int   g_rsA[NP1];
__device__ int   g_rsL[NP1];
__device__ int   g_fillA[NN];
__device__ int   g_fillL[NN];
__device__ int2  g_eA[EE];
__device__ int2  g_eL[EE];
__device__ int   g_bsumA[NCHUNK];
__device__ int   g_bsumL[NCHUNK];
__device__ unsigned g_count;
__device__ volatile unsigned g_sense;

// ---------------------------------------------------------------------------
__device__ __forceinline__ void grid_sync(unsigned* sense) {
    __syncthreads();
    if (threadIdx.x == 0) {
        unsigned s = *sense + 1;
        *sense = s;
        __threadfence();
        unsigned prev = atomicAdd(&g_count, 1u);
        if (prev == gridDim.x - 1) {
            g_count = 0;
            __threadfence();
            g_sense = s;
        } else {
            while (g_sense != s) __nanosleep(32);
            __threadfence();
        }
    }
    __syncthreads();
}

// ---------------------------------------------------------------------------
// Cooperative CSR build for ONE matrix: zero -> hist -> scan -> scatter
__global__ __launch_bounds__(CSRT, 2)
void csr_build_one(const int* __restrict__ row, const int* __restrict__ col,
                   const float* __restrict__ val, int E,
                   int* __restrict__ rs, int* __restrict__ fill,
                   int* __restrict__ bsum, int2* __restrict__ epack,
                   int zero_norms) {
    __shared__ unsigned sense;
    __shared__ int sm[CSRT];
    const int tid = threadIdx.x;
    const int gtid = blockIdx.x * CSRT + tid;
    const int gs = gridDim.x * CSRT;
    if (tid == 0) sense = g_sense;

    for (int i = gtid; i < NP1; i += gs) __stcg(&rs[i], 0);
    if (zero_norms && gtid < ITERS) __stcg(&g_norms[gtid], 0.f);
    grid_sync(&sense);

    for (int e = gtid; e < E; e += gs)
        atomicAdd(&rs[__ldg(row + e) + 1], 1);
    grid_sync(&sense);

    // per-chunk inclusive scan (NCHUNK <= gridDim.x: single pass)
    if (blockIdx.x < NCHUNK) {
        int idx = blockIdx.x * CSRT + tid;
        int x = (idx < NP1) ? __ldcg(&rs[idx]) : 0;
        sm[tid] = x;
        __syncthreads();
#pragma unroll
        for (int off = 1; off < CSRT; off <<= 1) {
            int t = (tid >= off) ? sm[tid - off] : 0;
            __syncthreads();
            sm[tid] += t;
            __syncthreads();
        }
        if (idx < NP1) __stcg(&rs[idx], sm[tid]);
        if (tid == CSRT - 1) __stcg(&bsum[blockIdx.x], sm[tid]);
    }
    grid_sync(&sense);

    if (blockIdx.x == 0) {
        int x = (tid < NCHUNK) ? __ldcg(&bsum[tid]) : 0;
        sm[tid] = x;
        __syncthreads();
#pragma unroll
        for (int off = 1; off < CSRT; off <<= 1) {
            int t = (tid >= off) ? sm[tid - off] : 0;
            __syncthreads();
            sm[tid] += t;
            __syncthreads();
        }
        if (tid < NCHUNK) __stcg(&bsum[tid], sm[tid]);
    }
    grid_sync(&sense);

    for (int i = gtid; i < NP1; i += gs) {
        int chunk = i / CSRT;
        int a = __ldcg(&rs[i]) + (chunk ? __ldcg(&bsum[chunk - 1]) : 0);
        __stcg(&rs[i], a);
        if (i < NN) __stcg(&fill[i], a);
    }
    grid_sync(&sense);

    for (int e = gtid; e < E; e += gs) {
        int r = __ldg(row + e);
        int pos = atomicAdd(&fill[r], 1);
        epack[pos] = make_int2(__ldg(col + e), __float_as_int(__ldg(val + e)));
    }
}

// ---------------------------------------------------------------------------
// Fused SpMM + residual Linear (+ optional score): 16 lanes per row.
__global__ __launch_bounds__(512, 2)
void layer_kernel(const float* __restrict__ Xin, float* __restrict__ Xout,
                  const float* __restrict__ W, const float* __restrict__ Ws,
                  float* __restrict__ vout, int layer2) {
    __shared__ float  Wt[DD * DD];
    __shared__ float4 rowbuf[32][16];
    __shared__ float4 WsS[16];
    const int tid = threadIdx.x;

    for (int i = tid; i < DD * DD; i += 512) {
        int k = i >> 6, d = i & 63;
        Wt[k * DD + d] = __ldg(&W[d * DD + k]);
    }
    if (tid < 16) WsS[tid] = __ldg(&((const float4*)Ws)[tid]);
    __syncthreads();

    const int gt = blockIdx.x * 512 + tid;
    const int r = gt >> 4;
    const int c = gt & 15;

    int s = __ldg(&g_rsA[r]);
    int e = __ldg(&g_rsA[r + 1]);
    float4 acc = make_float4(0.f, 0.f, 0.f, 0.f);
    int i = s;
    if (i < e && (i & 1)) {
        int2 p = __ldg(&g_eA[i]);
        float v = __int_as_float(p.y);
        float4 a = __ldg(((const float4*)(Xin + (size_t)p.x * DD)) + c);
        acc.x += v * a.x; acc.y += v * a.y; acc.z += v * a.z; acc.w += v * a.w;
        i++;
    }
    for (; i + 3 < e; i += 4) {
        int4 q0 = __ldcs((const int4*)(g_eA + i));       // streaming
        int4 q1 = __ldcs((const int4*)(g_eA + i + 2));
        float4 a  = __ldg(((const float4*)(Xin + (size_t)q0.x * DD)) + c);
        float4 b  = __ldg(((const float4*)(Xin + (size_t)q0.z * DD)) + c);
        float4 d2 = __ldg(((const float4*)(Xin + (size_t)q1.x * DD)) + c);
        float4 f  = __ldg(((const float4*)(Xin + (size_t)q1.z * DD)) + c);
        float v0 = __int_as_float(q0.y), v1 = __int_as_float(q0.w);
        float v2 = __int_as_float(q1.y), v3 = __int_as_float(q1.w);
        acc.x += v0 * a.x + v1 * b.x + v2 * d2.x + v3 * f.x;
        acc.y += v0 * a.y + v1 * b.y + v2 * d2.y + v3 * f.y;
        acc.z += v0 * a.z + v1 * b.z + v2 * d2.z + v3 * f.z;
        acc.w += v0 * a.w + v1 * b.w + v2 * d2.w + v3 * f.w;
    }
    for (; i < e; i++) {
        int2 p = __ldg(&g_eA[i]);
        float v = __int_as_float(p.y);
        float4 a = __ldg(((const float4*)(Xin + (size_t)p.x * DD)) + c);
        acc.x += v * a.x; acc.y += v * a.y; acc.z += v * a.z; acc.w += v * a.w;
    }

    const int slot = tid >> 4;
    rowbuf[slot][c] = acc;
    __syncwarp();

    float4 o = make_float4(0.f, 0.f, 0.f, 0.f);
#pragma unroll
    for (int k4 = 0; k4 < 16; k4++) {
        float4 xr = rowbuf[slot][k4];
        const float* xk = (const float*)&xr;
#pragma unroll
        for (int j = 0; j < 4; j++) {
            int k = k4 * 4 + j;
            float4 w = ((const float4*)(Wt + k * DD))[c];
            float x = xk[j];
            o.x += x * w.x; o.y += x * w.y; o.z += x * w.z; o.w += x * w.w;
        }
    }

    float4 xi = __ldg(((const float4*)(Xin + (size_t)r * DD)) + c);
    float4 res;
    res.x = xi.x + fmaxf(o.x, 0.f);
    res.y = xi.y + fmaxf(o.y, 0.f);
    res.z = xi.z + fmaxf(o.z, 0.f);
    res.w = xi.w + fmaxf(o.w, 0.f);
    ((float4*)(Xout + (size_t)r * DD))[c] = res;

    if (layer2) {
        float4 ws = WsS[c];
        float pv = res.x * ws.x + res.y * ws.y + res.z * ws.z + res.w * ws.w;
        pv += __shfl_xor_sync(0xFFFFFFFFu, pv, 8, 16);
        pv += __shfl_xor_sync(0xFFFFFFFFu, pv, 4, 16);
        pv += __shfl_xor_sync(0xFFFFFFFFu, pv, 2, 16);
        pv += __shfl_xor_sync(0xFFFFFFFFu, pv, 1, 16);
        if (c == 0) vout[r] = pv;
    }
}

// ---------------------------------------------------------------------------
// Power iterations: per-block CSR-L edge slice cached in smem; lazy norm
// (1 barrier/iter); ping-pong v buffers; 8-wide MLP on the v gathers.
__global__ __launch_bounds__(PWT, 2)
void power_kernel(float* __restrict__ out) {
    extern __shared__ int2 sE[];                 // ECAP edges
    __shared__ unsigned sense;
    __shared__ float wsum[PWT / 32];
    const int tid = threadIdx.x;
    const int lane = tid & 31, wid = tid >> 5;
    if (tid == 0) sense = g_sense;

    const int r0 = blockIdx.x * RPB;
    const int r1 = (r0 + RPB < NN) ? r0 + RPB : NN;
    const int s0 = __ldg(&g_rsL[r0]);
    const int e0 = __ldg(&g_rsL[r1]);
    const int cnt = min(e0 - s0, ECAP);
    for (int i = tid; i < cnt; i += PWT) sE[i] = __ldg(&g_eL[s0 + i]);

    const int r = r0 + tid;
    const bool active = (tid < RPB) && (r < NN);
    int s = 0, e = 0;
    if (active) {
        s = __ldg(&g_rsL[r]) - s0;
        e = __ldg(&g_rsL[r + 1]) - s0;
    }
    __syncthreads();

    float y = 0.f;
    for (int it = 0; it < ITERS; it++) {
        float alpha = 1.f;
        if (it > 0)
            alpha = 1.f / fmaxf(sqrtf(__ldcg(&g_norms[it - 1])), 1e-12f);
        const float* src = (it & 1) ? g_yb : g_ya;
        float* dst = (it & 1) ? g_ya : g_yb;

        float acc = 0.f;
        if (active) {
            int i = s;
            int elim = (e < ECAP) ? e : ECAP;
            for (; i + 7 < elim; i += 8) {
                int2 p0 = sE[i],     p1 = sE[i + 1], p2 = sE[i + 2], p3 = sE[i + 3];
                int2 p4 = sE[i + 4], p5 = sE[i + 5], p6 = sE[i + 6], p7 = sE[i + 7];
                float v0 = __ldcg(&src[p0.x]);
                float v1 = __ldcg(&src[p1.x]);
                float v2 = __ldcg(&src[p2.x]);
                float v3 = __ldcg(&src[p3.x]);
                float v4 = __ldcg(&src[p4.x]);
                float v5 = __ldcg(&src[p5.x]);
                float v6 = __ldcg(&src[p6.x]);
                float v7 = __ldcg(&src[p7.x]);
                acc += __int_as_float(p0.y) * v0 + __int_as_float(p1.y) * v1;
                acc += __int_as_float(p2.y) * v2 + __int_as_float(p3.y) * v3;
                acc += __int_as_float(p4.y) * v4 + __int_as_float(p5.y) * v5;
                acc += __int_as_float(p6.y) * v6 + __int_as_float(p7.y) * v7;
            }
            for (; i < elim; i++) {
                int2 p = sE[i];
                acc += __int_as_float(p.y) * __ldcg(&src[p.x]);
            }
            for (; i < e; i++) {                 // gmem overflow (never hit)
                int2 p = __ldg(&g_eL[s0 + i]);
                acc += __int_as_float(p.y) * __ldcg(&src[p.x]);
            }
        }

        float sq = 0.f;
        if (active) {
            float z = alpha * acc;
            float sg = (z > 0.f) ? 1.f : ((z < 0.f) ? -1.f : 0.f);
            y = z - TAU * sg;
            sq = y * y;
            __stcg(&dst[r], y);
        }
#pragma unroll
        for (int off = 16; off > 0; off >>= 1)
            sq += __shfl_down_sync(0xFFFFFFFFu, sq, off);
        if (lane == 0) wsum[wid] = sq;
        __syncthreads();
        if (wid == 0) {
            sq = (lane < (PWT >> 5)) ? wsum[lane] : 0.f;
#pragma unroll
            for (int off = 16; off > 0; off >>= 1)
                sq += __shfl_down_sync(0xFFFFFFFFu, sq, off);
            if (lane == 0) atomicAdd(&g_norms[it], sq);
        }
        grid_sync(&sense);
    }

    if (active) {
        float inv = 1.f / fmaxf(sqrtf(__ldcg(&g_norms[ITERS - 1])), 1e-12f);
        out[r] = y * inv;
    }
}

// ---------------------------------------------------------------------------
extern "C" void kernel_launch(void* const* d_in, const int* in_sizes, int n_in,
                              void* d_out, int out_size) {
    const int*   A_row = (const int*)d_in[0];
    const int*   A_col = (const int*)d_in[1];
    const float* A_val = (const float*)d_in[2];
    const int*   L_row = (const int*)d_in[3];
    const int*   L_col = (const int*)d_in[4];
    const float* L_val = (const float*)d_in[5];
    const float* embed = (const float*)d_in[6];
    const float* W1    = (const float*)d_in[7];
    const float* W2    = (const float*)d_in[8];
    const float* Ws    = (const float*)d_in[9];
    const int E = in_sizes[0];
    float* out = (float*)d_out;

    float *X, *X2, *ya;
    int *rsA, *rsL, *fillA, *fillL, *bsA, *bsL;
    int2 *eA, *eL;
    cudaGetSymbolAddress((void**)&X,    g_X);
    cudaGetSymbolAddress((void**)&X2,   g_X2);
    cudaGetSymbolAddress((void**)&ya,   g_ya);
    cudaGetSymbolAddress((void**)&rsA,  g_rsA);
    cudaGetSymbolAddress((void**)&rsL,  g_rsL);
    cudaGetSymbolAddress((void**)&fillA,g_fillA);
    cudaGetSymbolAddress((void**)&fillL,g_fillL);
    cudaGetSymbolAddress((void**)&bsA,  g_bsumA);
    cudaGetSymbolAddress((void**)&bsL,  g_bsumL);
    cudaGetSymbolAddress((void**)&eA,   g_eA);
    cudaGetSymbolAddress((void**)&eL,   g_eL);

    static int smem_set = 0;
    if (!smem_set) {
        cudaFuncSetAttribute(power_kernel,
                             cudaFuncAttributeMaxDynamicSharedMemorySize,
                             ECAP * (int)sizeof(int2));
        smem_set = 1;
    }

    // 1-2) CSR builds (A then L)
    csr_build_one<<<CB, CSRT>>>(A_row, A_col, A_val, E, rsA, fillA, bsA, eA, 1);
    csr_build_one<<<CB, CSRT>>>(L_row, L_col, L_val, E, rsL, fillL, bsL, eL, 0);

    // 3-4) GNN layers (launch slot 4 = layer2 -> gets profiled)
    const int LB = (NN * 16) / 512;
    layer_kernel<<<LB, 512>>>(embed, X,  W1, Ws, ya, 0);
    layer_kernel<<<LB, 512>>>(X,     X2, W2, Ws, ya, 1);

    // 5) power iterations
    power_kernel<<<CB, PWT, ECAP * sizeof(int2)>>>(out);
}

// round 6
// speedup vs baseline: 1.1601x; 1.0514x over previous
#include <cuda_runtime.h>
#include <math.h>

#define NN 100000
#define EE 1600000
#define DD 64
#define TAU 0.5f
#define ITERS 10

#define CB 296                         // cooperative blocks (2/SM), 8 | CB
#define LEAFN 8
#define LEAFC (CB / LEAFN)             // 37
#define CSRT 512
#define PWT 384
#define NP1 (NN + 1)
#define NCHUNK ((NP1 + CSRT - 1) / CSRT)   // 196
#define RPB ((NN + CB - 1) / CB)           // 338
#define ECAP 7936                          // smem edge cache (62KB)

// ---------------- scratch ----------------
__device__ float g_X[NN * DD];
__device__ float g_X2[NN * DD];
__device__ float g_ya[NN];
__device__ float g_yb[NN];
__device__ float g_norms[ITERS];
__device__ float g_nleaf[ITERS * LEAFN * 32];   // padded leaf partials
__device__ int   g_rsA[NP1];
__device__ int   g_rsL[NP1];
__device__ int   g_fillA[NN];
__device__ int   g_fillL[NN];
__device__ int2  g_eA[EE];
__device__ int2  g_eL[EE];
__device__ int   g_bsumA[NCHUNK];
__device__ int   g_bsumL[NCHUNK];
__device__ unsigned g_leaf[LEAFN * 32];         // padded leaf counters
__device__ unsigned g_root;
__device__ volatile unsigned g_sense;

// ---------------------------------------------------------------------------
// Tree grid barrier: 37-way leaf atomics (8 parallel) + 8-way root.
// If nrm != 0, *nrm was already atomically accumulated by caller (tid 0);
// root finisher folds leaf partials into g_norms[it].
__device__ __forceinline__ void grid_sync_tree(unsigned* sense_s, int it_norm) {
    __syncthreads();
    if (threadIdx.x == 0) {
        unsigned s = *sense_s + 1;
        *sense_s = s;
        __threadfence();
        int leaf = blockIdx.x & (LEAFN - 1);
        unsigned p = atomicAdd(&g_leaf[leaf * 32], 1u);
        if (p == LEAFC - 1) {
            g_leaf[leaf * 32] = 0;
            __threadfence();
            unsigned q = atomicAdd(&g_root, 1u);
            if (q == LEAFN - 1) {
                g_root = 0;
                if (it_norm >= 0) {
                    float t = 0.f;
#pragma unroll
                    for (int l = 0; l < LEAFN; l++)
                        t += __ldcg(&g_nleaf[(it_norm * LEAFN + l) * 32]);
                    __stcg(&g_norms[it_norm], t);
                }
                __threadfence();
                g_sense = s;
            } else {
                while (g_sense != s) __nanosleep(32);
            }
        } else {
            while (g_sense != s) __nanosleep(32);
        }
    }
    __syncthreads();
}

// ---------------------------------------------------------------------------
__global__ __launch_bounds__(CSRT, 2)
void csr_build_one(const int* __restrict__ row, const int* __restrict__ col,
                   const float* __restrict__ val, int E,
                   int* __restrict__ rs, int* __restrict__ fill,
                   int* __restrict__ bsum, int2* __restrict__ epack,
                   int zero_norms) {
    __shared__ unsigned sense;
    __shared__ int sm[CSRT];
    const int tid = threadIdx.x;
    const int gtid = blockIdx.x * CSRT + tid;
    const int gs = gridDim.x * CSRT;
    if (tid == 0) sense = g_sense;

    for (int i = gtid; i < NP1; i += gs) __stcg(&rs[i], 0);
    if (zero_norms) {
        for (int i = gtid; i < ITERS * LEAFN * 32; i += gs) __stcg(&g_nleaf[i], 0.f);
        if (gtid < ITERS) __stcg(&g_norms[gtid], 0.f);
    }
    grid_sync_tree(&sense, -1);

    for (int e = gtid; e < E; e += gs)
        atomicAdd(&rs[__ldg(row + e) + 1], 1);
    grid_sync_tree(&sense, -1);

    if (blockIdx.x < NCHUNK) {
        int idx = blockIdx.x * CSRT + tid;
        int x = (idx < NP1) ? __ldcg(&rs[idx]) : 0;
        sm[tid] = x;
        __syncthreads();
#pragma unroll
        for (int off = 1; off < CSRT; off <<= 1) {
            int t = (tid >= off) ? sm[tid - off] : 0;
            __syncthreads();
            sm[tid] += t;
            __syncthreads();
        }
        if (idx < NP1) __stcg(&rs[idx], sm[tid]);
        if (tid == CSRT - 1) __stcg(&bsum[blockIdx.x], sm[tid]);
    }
    grid_sync_tree(&sense, -1);

    if (blockIdx.x == 0) {
        int x = (tid < NCHUNK) ? __ldcg(&bsum[tid]) : 0;
        sm[tid] = x;
        __syncthreads();
#pragma unroll
        for (int off = 1; off < CSRT; off <<= 1) {
            int t = (tid >= off) ? sm[tid - off] : 0;
            __syncthreads();
            sm[tid] += t;
            __syncthreads();
        }
        if (tid < NCHUNK) __stcg(&bsum[tid], sm[tid]);
    }
    grid_sync_tree(&sense, -1);

    for (int i = gtid; i < NP1; i += gs) {
        int chunk = i / CSRT;
        int a = __ldcg(&rs[i]) + (chunk ? __ldcg(&bsum[chunk - 1]) : 0);
        __stcg(&rs[i], a);
        if (i < NN) __stcg(&fill[i], a);
    }
    grid_sync_tree(&sense, -1);

    for (int e = gtid; e < E; e += gs) {
        int r = __ldg(row + e);
        int pos = atomicAdd(&fill[r], 1);
        epack[pos] = make_int2(__ldg(col + e), __float_as_int(__ldg(val + e)));
    }
}

// ---------------------------------------------------------------------------
// Fused SpMM (512 thr, 16 lanes/row) + row-tiled Linear (128 thr, 4 rows each).
__global__ __launch_bounds__(512, 2)
void layer_kernel(const float* __restrict__ Xin, float* __restrict__ Xout,
                  const float* __restrict__ W, const float* __restrict__ Ws,
                  float* __restrict__ vout, int layer2) {
    __shared__ float  Wt[DD * DD];        // Wt[k*64+d] = W[d][k]
    __shared__ float4 AX4[32 * 17];       // AX4[row*17 + c], padded
    __shared__ float4 WsS[16];
    const int tid = threadIdx.x;

    for (int i = tid; i < DD * DD; i += 512) {
        int k = i >> 6, d = i & 63;
        Wt[k * DD + d] = __ldg(&W[d * DD + k]);
    }
    if (tid < 16) WsS[tid] = __ldg(&((const float4*)Ws)[tid]);
    __syncthreads();

    const int gt = blockIdx.x * 512 + tid;
    const int r = gt >> 4;
    const int c = tid & 15;
    const int slot = tid >> 4;            // 0..31

    // ---- gather phase: AX row into registers, park in smem ----
    {
        int s = __ldg(&g_rsA[r]);
        int e = __ldg(&g_rsA[r + 1]);
        float4 acc = make_float4(0.f, 0.f, 0.f, 0.f);
        int i = s;
        if (i < e && (i & 1)) {
            int2 p = __ldg(&g_eA[i]);
            float v = __int_as_float(p.y);
            float4 a = __ldg(((const float4*)(Xin + (size_t)p.x * DD)) + c);
            acc.x += v * a.x; acc.y += v * a.y; acc.z += v * a.z; acc.w += v * a.w;
            i++;
        }
        for (; i + 3 < e; i += 4) {
            int4 q0 = __ldcs((const int4*)(g_eA + i));
            int4 q1 = __ldcs((const int4*)(g_eA + i + 2));
            float4 a  = __ldg(((const float4*)(Xin + (size_t)q0.x * DD)) + c);
            float4 b  = __ldg(((const float4*)(Xin + (size_t)q0.z * DD)) + c);
            float4 d2 = __ldg(((const float4*)(Xin + (size_t)q1.x * DD)) + c);
            float4 f  = __ldg(((const float4*)(Xin + (size_t)q1.z * DD)) + c);
            float v0 = __int_as_float(q0.y), v1 = __int_as_float(q0.w);
            float v2 = __int_as_float(q1.y), v3 = __int_as_float(q1.w);
            acc.x += v0 * a.x + v1 * b.x + v2 * d2.x + v3 * f.x;
            acc.y += v0 * a.y + v1 * b.y + v2 * d2.y + v3 * f.y;
            acc.z += v0 * a.z + v1 * b.z + v2 * d2.z + v3 * f.z;
            acc.w += v0 * a.w + v1 * b.w + v2 * d2.w + v3 * f.w;
        }
        for (; i < e; i++) {
            int2 p = __ldg(&g_eA[i]);
            float v = __int_as_float(p.y);
            float4 a = __ldg(((const float4*)(Xin + (size_t)p.x * DD)) + c);
            acc.x += v * a.x; acc.y += v * a.y; acc.z += v * a.z; acc.w += v * a.w;
        }
        AX4[slot * 17 + c] = acc;
    }
    __syncthreads();

    // ---- linear phase: 128 threads, thread = (c, quad q), 4 rows each ----
    if (tid < 128) {
        const int q = tid >> 4;           // 0..7
        const int rb = q * 4;             // local row base
        float4 o0 = make_float4(0.f,0.f,0.f,0.f), o1 = o0, o2 = o0, o3 = o0;
#pragma unroll
        for (int k4 = 0; k4 < 16; k4++) {
            float4 a0 = AX4[(rb + 0) * 17 + k4];
            float4 a1 = AX4[(rb + 1) * 17 + k4];
            float4 a2 = AX4[(rb + 2) * 17 + k4];
            float4 a3 = AX4[(rb + 3) * 17 + k4];
            float4 w0 = ((const float4*)(Wt + (k4 * 4 + 0) * DD))[c];
            o0.x += a0.x*w0.x; o0.y += a0.x*w0.y; o0.z += a0.x*w0.z; o0.w += a0.x*w0.w;
            o1.x += a1.x*w0.x; o1.y += a1.x*w0.y; o1.z += a1.x*w0.z; o1.w += a1.x*w0.w;
            o2.x += a2.x*w0.x; o2.y += a2.x*w0.y; o2.z += a2.x*w0.z; o2.w += a2.x*w0.w;
            o3.x += a3.x*w0.x; o3.y += a3.x*w0.y; o3.z += a3.x*w0.z; o3.w += a3.x*w0.w;
            float4 w1 = ((const float4*)(Wt + (k4 * 4 + 1) * DD))[c];
            o0.x += a0.y*w1.x; o0.y += a0.y*w1.y; o0.z += a0.y*w1.z; o0.w += a0.y*w1.w;
            o1.x += a1.y*w1.x; o1.y += a1.y*w1.y; o1.z += a1.y*w1.z; o1.w += a1.y*w1.w;
            o2.x += a2.y*w1.x; o2.y += a2.y*w1.y; o2.z += a2.y*w1.z; o2.w += a2.y*w1.w;
            o3.x += a3.y*w1.x; o3.y += a3.y*w1.y; o3.z += a3.y*w1.z; o3.w += a3.y*w1.w;
            float4 w2 = ((const float4*)(Wt + (k4 * 4 + 2) * DD))[c];
            o0.x += a0.z*w2.x; o0.y += a0.z*w2.y; o0.z += a0.z*w2.z; o0.w += a0.z*w2.w;
            o1.x += a1.z*w2.x; o1.y += a1.z*w2.y; o1.z += a1.z*w2.z; o1.w += a1.z*w2.w;
            o2.x += a2.z*w2.x; o2.y += a2.z*w2.y; o2.z += a2.z*w2.z; o2.w += a2.z*w2.w;
            o3.x += a3.z*w2.x; o3.y += a3.z*w2.y; o3.z += a3.z*w2.z; o3.w += a3.z*w2.w;
            float4 w3 = ((const float4*)(Wt + (k4 * 4 + 3) * DD))[c];
            o0.x += a0.w*w3.x; o0.y += a0.w*w3.y; o0.z += a0.w*w3.z; o0.w += a0.w*w3.w;
            o1.x += a1.w*w3.x; o1.y += a1.w*w3.y; o1.z += a1.w*w3.z; o1.w += a1.w*w3.w;
            o2.x += a2.w*w3.x; o2.y += a2.w*w3.y; o2.z += a2.w*w3.z; o2.w += a2.w*w3.w;
            o3.x += a3.w*w3.x; o3.y += a3.w*w3.y; o3.z += a3.w*w3.z; o3.w += a3.w*w3.w;
        }

        const int rg0 = blockIdx.x * 32 + rb;     // global row base
        float4 oo[4] = {o0, o1, o2, o3};
#pragma unroll
        for (int i2 = 0; i2 < 4; i2++) {
            int rg = rg0 + i2;
            float4 xi = __ldg(((const float4*)(Xin + (size_t)rg * DD)) + c);
            float4 res;
            res.x = xi.x + fmaxf(oo[i2].x, 0.f);
            res.y = xi.y + fmaxf(oo[i2].y, 0.f);
            res.z = xi.z + fmaxf(oo[i2].z, 0.f);
            res.w = xi.w + fmaxf(oo[i2].w, 0.f);
            ((float4*)(Xout + (size_t)rg * DD))[c] = res;
            if (layer2) {
                float4 ws = WsS[c];
                float pv = res.x*ws.x + res.y*ws.y + res.z*ws.z + res.w*ws.w;
                pv += __shfl_xor_sync(0xFFFFFFFFu, pv, 8, 16);
                pv += __shfl_xor_sync(0xFFFFFFFFu, pv, 4, 16);
                pv += __shfl_xor_sync(0xFFFFFFFFu, pv, 2, 16);
                pv += __shfl_xor_sync(0xFFFFFFFFu, pv, 1, 16);
                if (c == 0) vout[rg] = pv;
            }
        }
    }
}

// ---------------------------------------------------------------------------
__global__ __launch_bounds__(PWT, 2)
void power_kernel(float* __restrict__ out) {
    extern __shared__ int2 sE[];
    __shared__ unsigned sense;
    __shared__ float wsum[PWT / 32];
    const int tid = threadIdx.x;
    const int lane = tid & 31, wid = tid >> 5;
    if (tid == 0) sense = g_sense;

    const int r0 = blockIdx.x * RPB;
    const int r1 = (r0 + RPB < NN) ? r0 + RPB : NN;
    const int s0 = __ldg(&g_rsL[r0]);
    const int e0 = __ldg(&g_rsL[r1]);
    const int cnt = min(e0 - s0, ECAP);
    for (int i = tid; i < cnt; i += PWT) sE[i] = __ldg(&g_eL[s0 + i]);

    const int r = r0 + tid;
    const bool active = (tid < RPB) && (r < NN);
    int s = 0, e = 0;
    if (active) {
        s = __ldg(&g_rsL[r]) - s0;
        e = __ldg(&g_rsL[r + 1]) - s0;
    }
    __syncthreads();

    const int leaf = blockIdx.x & (LEAFN - 1);
    float y = 0.f;
    for (int it = 0; it < ITERS; it++) {
        float alpha = 1.f;
        if (it > 0)
            alpha = 1.f / fmaxf(sqrtf(__ldcg(&g_norms[it - 1])), 1e-12f);
        const float* src = (it & 1) ? g_yb : g_ya;
        float* dst = (it & 1) ? g_ya : g_yb;

        float acc = 0.f;
        if (active) {
            int i = s;
            int elim = (e < ECAP) ? e : ECAP;
            for (; i + 7 < elim; i += 8) {
                int2 p0 = sE[i],     p1 = sE[i + 1], p2 = sE[i + 2], p3 = sE[i + 3];
                int2 p4 = sE[i + 4], p5 = sE[i + 5], p6 = sE[i + 6], p7 = sE[i + 7];
                float v0 = __ldcg(&src[p0.x]);
                float v1 = __ldcg(&src[p1.x]);
                float v2 = __ldcg(&src[p2.x]);
                float v3 = __ldcg(&src[p3.x]);
                float v4 = __ldcg(&src[p4.x]);
                float v5 = __ldcg(&src[p5.x]);
                float v6 = __ldcg(&src[p6.x]);
                float v7 = __ldcg(&src[p7.x]);
                acc += __int_as_float(p0.y) * v0 + __int_as_float(p1.y) * v1;
                acc += __int_as_float(p2.y) * v2 + __int_as_float(p3.y) * v3;
                acc += __int_as_float(p4.y) * v4 + __int_as_float(p5.y) * v5;
                acc += __int_as_float(p6.y) * v6 + __int_as_float(p7.y) * v7;
            }
            for (; i < elim; i++) {
                int2 p = sE[i];
                acc += __int_as_float(p.y) * __ldcg(&src[p.x]);
            }
            for (; i < e; i++) {
                int2 p = __ldg(&g_eL[s0 + i]);
                acc += __int_as_float(p.y) * __ldcg(&src[p.x]);
            }
        }

        float sq = 0.f;
        if (active) {
            float z = alpha * acc;
            float sg = (z > 0.f) ? 1.f : ((z < 0.f) ? -1.f : 0.f);
            y = z - TAU * sg;
            sq = y * y;
            __stcg(&dst[r], y);
        }
#pragma unroll
        for (int off = 16; off > 0; off >>= 1)
            sq += __shfl_down_sync(0xFFFFFFFFu, sq, off);
        if (lane == 0) wsum[wid] = sq;
        __syncthreads();
        if (wid == 0) {
            sq = (lane < (PWT >> 5)) ? wsum[lane] : 0.f;
#pragma unroll
            for (int off = 16; off > 0; off >>= 1)
                sq += __shfl_down_sync(0xFFFFFFFFu, sq, off);
            if (lane == 0)
                atomicAdd(&g_nleaf[(it * LEAFN + leaf) * 32], sq);
        }
        grid_sync_tree(&sense, it);       // root folds leaf partials -> g_norms[it]
    }

    if (active) {
        float inv = 1.f / fmaxf(sqrtf(__ldcg(&g_norms[ITERS - 1])), 1e-12f);
        out[r] = y * inv;
    }
}

// ---------------------------------------------------------------------------
extern "C" void kernel_launch(void* const* d_in, const int* in_sizes, int n_in,
                              void* d_out, int out_size) {
    const int*   A_row = (const int*)d_in[0];
    const int*   A_col = (const int*)d_in[1];
    const float* A_val = (const float*)d_in[2];
    const int*   L_row = (const int*)d_in[3];
    const int*   L_col = (const int*)d_in[4];
    const float* L_val = (const float*)d_in[5];
    const float* embed = (const float*)d_in[6];
    const float* W1    = (const float*)d_in[7];
    const float* W2    = (const float*)d_in[8];
    const float* Ws    = (const float*)d_in[9];
    const int E = in_sizes[0];
    float* out = (float*)d_out;

    float *X, *X2, *ya;
    int *rsA, *rsL, *fillA, *fillL, *bsA, *bsL;
    int2 *eA, *eL;
    cudaGetSymbolAddress((void**)&X,    g_X);
    cudaGetSymbolAddress((void**)&X2,   g_X2);
    cudaGetSymbolAddress((void**)&ya,   g_ya);
    cudaGetSymbolAddress((void**)&rsA,  g_rsA);
    cudaGetSymbolAddress((void**)&rsL,  g_rsL);
    cudaGetSymbolAddress((void**)&fillA,g_fillA);
    cudaGetSymbolAddress((void**)&fillL,g_fillL);
    cudaGetSymbolAddress((void**)&bsA,  g_bsumA);
    cudaGetSymbolAddress((void**)&bsL,  g_bsumL);
    cudaGetSymbolAddress((void**)&eA,   g_eA);
    cudaGetSymbolAddress((void**)&eL,   g_eL);

    static int smem_set = 0;
    if (!smem_set) {
        cudaFuncSetAttribute(power_kernel,
                             cudaFuncAttributeMaxDynamicSharedMemorySize,
                             ECAP * (int)sizeof(int2));
        smem_set = 1;
    }

    csr_build_one<<<CB, CSRT>>>(A_row, A_col, A_val, E, rsA, fillA, bsA, eA, 1);
    csr_build_one<<<CB, CSRT>>>(L_row, L_col, L_val, E, rsL, fillL, bsL, eL, 0);

    const int LB = (NN * 16) / 512;   // 3125
    layer_kernel<<<LB, 512>>>(embed, X,  W1, Ws, ya, 0);
    layer_kernel<<<LB, 512>>>(X,     X2, W2, Ws, ya, 1);   // profiled slot

    power_kernel<<<CB, PWT, ECAP * sizeof(int2)>>>(out);
}

// round 7
// speedup vs baseline: 1.2426x; 1.0711x over previous
#include <cuda_runtime.h>
#include <math.h>

#define NN 100000
#define EE 1600000
#define DD 64
#define TAU 0.5f
#define ITERS 10

#define CB 296
#define LEAFN 8
#define LEAFC (CB / LEAFN)             // 37
#define CSRT 512
#define PWT 384
#define NP1 (NN + 1)
#define NCHUNK ((NP1 + CSRT - 1) / CSRT)   // 196
#define RPB ((NN + CB - 1) / CB)           // 338
#define ECAP 7936

// ---------------- scratch ----------------
__device__ float g_X[NN * DD];
__device__ float g_X2[NN * DD];
__device__ float g_ya[NN];
__device__ float g_yb[NN];
__device__ float g_norms[ITERS];
__device__ float g_nleaf[ITERS * LEAFN * 32];
__device__ int   g_rsA[NP1];
__device__ int   g_rsL[NP1];
__device__ int   g_fillA[NN];
__device__ int   g_fillL[NN];
__device__ int2  g_eA[EE];
__device__ int2  g_eL[EE];
__device__ int   g_bsumA[NCHUNK];
__device__ int   g_bsumL[NCHUNK];
__device__ unsigned g_leaf[LEAFN * 32];
__device__ unsigned g_root;
__device__ volatile unsigned g_sense;

// ---------------------------------------------------------------------------
__device__ __forceinline__ void grid_sync_tree(unsigned* sense_s, int it_norm) {
    __syncthreads();
    if (threadIdx.x == 0) {
        unsigned s = *sense_s + 1;
        *sense_s = s;
        __threadfence();
        int leaf = blockIdx.x & (LEAFN - 1);
        unsigned p = atomicAdd(&g_leaf[leaf * 32], 1u);
        if (p == LEAFC - 1) {
            g_leaf[leaf * 32] = 0;
            __threadfence();
            unsigned q = atomicAdd(&g_root, 1u);
            if (q == LEAFN - 1) {
                g_root = 0;
                if (it_norm >= 0) {
                    float t = 0.f;
#pragma unroll
                    for (int l = 0; l < LEAFN; l++)
                        t += __ldcg(&g_nleaf[(it_norm * LEAFN + l) * 32]);
                    __stcg(&g_norms[it_norm], t);
                }
                __threadfence();
                g_sense = s;
            } else {
                while (g_sense != s) __nanosleep(32);
            }
        } else {
            while (g_sense != s) __nanosleep(32);
        }
    }
    __syncthreads();
}

// ---------------------------------------------------------------------------
// Fused CSR build for BOTH A and L: zero -> hist -> scan -> scatter
__global__ __launch_bounds__(CSRT, 2)
void csr_build_kernel(const int* __restrict__ Arow, const int* __restrict__ Acol,
                      const float* __restrict__ Aval,
                      const int* __restrict__ Lrow, const int* __restrict__ Lcol,
                      const float* __restrict__ Lval, int E) {
    __shared__ unsigned sense;
    __shared__ int sm[CSRT];
    const int tid = threadIdx.x;
    const int gtid = blockIdx.x * CSRT + tid;
    const int gs = gridDim.x * CSRT;
    if (tid == 0) sense = g_sense;

    for (int i = gtid; i < NP1; i += gs) { __stcg(&g_rsA[i], 0); __stcg(&g_rsL[i], 0); }
    for (int i = gtid; i < ITERS * LEAFN * 32; i += gs) __stcg(&g_nleaf[i], 0.f);
    if (gtid < ITERS) __stcg(&g_norms[gtid], 0.f);
    grid_sync_tree(&sense, -1);

    for (int e = gtid; e < E; e += gs) {
        atomicAdd(&g_rsA[__ldg(Arow + e) + 1], 1);
        atomicAdd(&g_rsL[__ldg(Lrow + e) + 1], 1);
    }
    grid_sync_tree(&sense, -1);

    for (int chunk = blockIdx.x; chunk < 2 * NCHUNK; chunk += gridDim.x) {
        int* arr = (chunk < NCHUNK) ? g_rsA : g_rsL;
        int* bs  = (chunk < NCHUNK) ? g_bsumA : g_bsumL;
        int cc = (chunk < NCHUNK) ? chunk : chunk - NCHUNK;
        int idx = cc * CSRT + tid;
        int x = (idx < NP1) ? __ldcg(&arr[idx]) : 0;
        sm[tid] = x;
        __syncthreads();
#pragma unroll
        for (int off = 1; off < CSRT; off <<= 1) {
            int t = (tid >= off) ? sm[tid - off] : 0;
            __syncthreads();
            sm[tid] += t;
            __syncthreads();
        }
        if (idx < NP1) __stcg(&arr[idx], sm[tid]);
        if (tid == CSRT - 1) __stcg(&bs[cc], sm[tid]);
        __syncthreads();
    }
    grid_sync_tree(&sense, -1);

    if (blockIdx.x < 2) {
        int* bs = blockIdx.x ? g_bsumL : g_bsumA;
        int x = (tid < NCHUNK) ? __ldcg(&bs[tid]) : 0;
        sm[tid] = x;
        __syncthreads();
#pragma unroll
        for (int off = 1; off < CSRT; off <<= 1) {
            int t = (tid >= off) ? sm[tid - off] : 0;
            __syncthreads();
            sm[tid] += t;
            __syncthreads();
        }
        if (tid < NCHUNK) __stcg(&bs[tid], sm[tid]);
    }
    grid_sync_tree(&sense, -1);

    for (int i = gtid; i < NP1; i += gs) {
        int chunk = i / CSRT;
        int a = __ldcg(&g_rsA[i]) + (chunk ? __ldcg(&g_bsumA[chunk - 1]) : 0);
        int l = __ldcg(&g_rsL[i]) + (chunk ? __ldcg(&g_bsumL[chunk - 1]) : 0);
        __stcg(&g_rsA[i], a);
        __stcg(&g_rsL[i], l);
        if (i < NN) { __stcg(&g_fillA[i], a); __stcg(&g_fillL[i], l); }
    }
    grid_sync_tree(&sense, -1);

    for (int e = gtid; e < E; e += gs) {
        int ra = __ldg(Arow + e);
        int pa = atomicAdd(&g_fillA[ra], 1);
        g_eA[pa] = make_int2(__ldg(Acol + e), __float_as_int(__ldg(Aval + e)));
        int rl = __ldg(Lrow + e);
        int pl = atomicAdd(&g_fillL[rl], 1);
        g_eL[pl] = make_int2(__ldg(Lcol + e), __float_as_int(__ldg(Lval + e)));
    }
}

// ---------------------------------------------------------------------------
// Fused SpMM (512 thr, 16 lanes/row, 32 rows/block) + Linear (256 thr x 2 rows).
// launch_bounds(512,3): cap regs at 42 -> 3 CTAs/SM for latency hiding.
__global__ __launch_bounds__(512, 3)
void layer_kernel(const float* __restrict__ Xin, float* __restrict__ Xout,
                  const float* __restrict__ W, const float* __restrict__ Ws,
                  float* __restrict__ vout, int layer2) {
    __shared__ float  Wt[DD * DD];        // Wt[k*64+d] = W[d][k]
    __shared__ float4 AX4[32 * 17];
    __shared__ float4 WsS[16];
    const int tid = threadIdx.x;

    for (int i = tid; i < DD * DD; i += 512) {
        int k = i >> 6, d = i & 63;
        Wt[k * DD + d] = __ldg(&W[d * DD + k]);
    }
    if (tid < 16) WsS[tid] = __ldg(&((const float4*)Ws)[tid]);
    __syncthreads();

    const int gt = blockIdx.x * 512 + tid;
    const int r = gt >> 4;
    const int c = tid & 15;
    const int slot = tid >> 4;

    // ---- gather phase ----
    {
        int s = __ldg(&g_rsA[r]);
        int e = __ldg(&g_rsA[r + 1]);
        float4 acc = make_float4(0.f, 0.f, 0.f, 0.f);
        int i = s;
        if (i < e && (i & 1)) {
            int2 p = __ldg(&g_eA[i]);
            float v = __int_as_float(p.y);
            float4 a = __ldg(((const float4*)(Xin + (size_t)p.x * DD)) + c);
            acc.x += v * a.x; acc.y += v * a.y; acc.z += v * a.z; acc.w += v * a.w;
            i++;
        }
        for (; i + 3 < e; i += 4) {
            int4 q0 = __ldcs((const int4*)(g_eA + i));
            int4 q1 = __ldcs((const int4*)(g_eA + i + 2));
            float4 a  = __ldg(((const float4*)(Xin + (size_t)q0.x * DD)) + c);
            float4 b  = __ldg(((const float4*)(Xin + (size_t)q0.z * DD)) + c);
            float4 d2 = __ldg(((const float4*)(Xin + (size_t)q1.x * DD)) + c);
            float4 f  = __ldg(((const float4*)(Xin + (size_t)q1.z * DD)) + c);
            float v0 = __int_as_float(q0.y), v1 = __int_as_float(q0.w);
            float v2 = __int_as_float(q1.y), v3 = __int_as_float(q1.w);
            acc.x += v0 * a.x + v1 * b.x + v2 * d2.x + v3 * f.x;
            acc.y += v0 * a.y + v1 * b.y + v2 * d2.y + v3 * f.y;
            acc.z += v0 * a.z + v1 * b.z + v2 * d2.z + v3 * f.z;
            acc.w += v0 * a.w + v1 * b.w + v2 * d2.w + v3 * f.w;
        }
        for (; i < e; i++) {
            int2 p = __ldg(&g_eA[i]);
            float v = __int_as_float(p.y);
            float4 a = __ldg(((const float4*)(Xin + (size_t)p.x * DD)) + c);
            acc.x += v * a.x; acc.y += v * a.y; acc.z += v * a.z; acc.w += v * a.w;
        }
        AX4[slot * 17 + c] = acc;
    }
    __syncthreads();

    // ---- linear phase: 256 threads, 2 rows each ----
    if (tid < 256) {
        const int q = tid >> 4;           // 0..15
        const int rb = q * 2;
        float4 o0 = make_float4(0.f,0.f,0.f,0.f), o1 = o0;
#pragma unroll
        for (int k4 = 0; k4 < 16; k4++) {
            float4 a0 = AX4[(rb + 0) * 17 + k4];
            float4 a1 = AX4[(rb + 1) * 17 + k4];
            float4 w0 = ((const float4*)(Wt + (k4 * 4 + 0) * DD))[c];
            o0.x += a0.x*w0.x; o0.y += a0.x*w0.y; o0.z += a0.x*w0.z; o0.w += a0.x*w0.w;
            o1.x += a1.x*w0.x; o1.y += a1.x*w0.y; o1.z += a1.x*w0.z; o1.w += a1.x*w0.w;
            float4 w1 = ((const float4*)(Wt + (k4 * 4 + 1) * DD))[c];
            o0.x += a0.y*w1.x; o0.y += a0.y*w1.y; o0.z += a0.y*w1.z; o0.w += a0.y*w1.w;
            o1.x += a1.y*w1.x; o1.y += a1.y*w1.y; o1.z += a1.y*w1.z; o1.w += a1.y*w1.w;
            float4 w2 = ((const float4*)(Wt + (k4 * 4 + 2) * DD))[c];
            o0.x += a0.z*w2.x; o0.y += a0.z*w2.y; o0.z += a0.z*w2.z; o0.w += a0.z*w2.w;
            o1.x += a1.z*w2.x; o1.y += a1.z*w2.y; o1.z += a1.z*w2.z; o1.w += a1.z*w2.w;
            float4 w3 = ((const float4*)(Wt + (k4 * 4 + 3) * DD))[c];
            o0.x += a0.w*w3.x; o0.y += a0.w*w3.y; o0.z += a0.w*w3.z; o0.w += a0.w*w3.w;
            o1.x += a1.w*w3.x; o1.y += a1.w*w3.y; o1.z += a1.w*w3.z; o1.w += a1.w*w3.w;
        }

        const int rg0 = blockIdx.x * 32 + rb;
        float4 oo[2] = {o0, o1};
#pragma unroll
        for (int i2 = 0; i2 < 2; i2++) {
            int rg = rg0 + i2;
            float4 xi = __ldg(((const float4*)(Xin + (size_t)rg * DD)) + c);
            float4 res;
            res.x = xi.x + fmaxf(oo[i2].x, 0.f);
            res.y = xi.y + fmaxf(oo[i2].y, 0.f);
            res.z = xi.z + fmaxf(oo[i2].z, 0.f);
            res.w = xi.w + fmaxf(oo[i2].w, 0.f);
            ((float4*)(Xout + (size_t)rg * DD))[c] = res;
            if (layer2) {
                float4 ws = WsS[c];
                float pv = res.x*ws.x + res.y*ws.y + res.z*ws.z + res.w*ws.w;
                pv += __shfl_xor_sync(0xFFFFFFFFu, pv, 8, 16);
                pv += __shfl_xor_sync(0xFFFFFFFFu, pv, 4, 16);
                pv += __shfl_xor_sync(0xFFFFFFFFu, pv, 2, 16);
                pv += __shfl_xor_sync(0xFFFFFFFFu, pv, 1, 16);
                if (c == 0) vout[rg] = pv;
            }
        }
    }
}

// ---------------------------------------------------------------------------
__global__ __launch_bounds__(PWT, 2)
void power_kernel(float* __restrict__ out) {
    extern __shared__ int2 sE[];
    __shared__ unsigned sense;
    __shared__ float wsum[PWT / 32];
    const int tid = threadIdx.x;
    const int lane = tid & 31, wid = tid >> 5;
    if (tid == 0) sense = g_sense;

    const int r0 = blockIdx.x * RPB;
    const int r1 = (r0 + RPB < NN) ? r0 + RPB : NN;
    const int s0 = __ldg(&g_rsL[r0]);
    const int e0 = __ldg(&g_rsL[r1]);
    const int cnt = min(e0 - s0, ECAP);
    for (int i = tid; i < cnt; i += PWT) sE[i] = __ldg(&g_eL[s0 + i]);

    const int r = r0 + tid;
    const bool active = (tid < RPB) && (r < NN);
    int s = 0, e = 0;
    if (active) {
        s = __ldg(&g_rsL[r]) - s0;
        e = __ldg(&g_rsL[r + 1]) - s0;
    }
    __syncthreads();

    const int leaf = blockIdx.x & (LEAFN - 1);
    float y = 0.f;
    for (int it = 0; it < ITERS; it++) {
        float alpha = 1.f;
        if (it > 0)
            alpha = 1.f / fmaxf(sqrtf(__ldcg(&g_norms[it - 1])), 1e-12f);
        const float* src = (it & 1) ? g_yb : g_ya;
        float* dst = (it & 1) ? g_ya : g_yb;

        float acc = 0.f;
        if (active) {
            int i = s;
            int elim = (e < ECAP) ? e : ECAP;
            for (; i + 7 < elim; i += 8) {
                int2 p0 = sE[i],     p1 = sE[i + 1], p2 = sE[i + 2], p3 = sE[i + 3];
                int2 p4 = sE[i + 4], p5 = sE[i + 5], p6 = sE[i + 6], p7 = sE[i + 7];
                float v0 = __ldcg(&src[p0.x]);
                float v1 = __ldcg(&src[p1.x]);
                float v2 = __ldcg(&src[p2.x]);
                float v3 = __ldcg(&src[p3.x]);
                float v4 = __ldcg(&src[p4.x]);
                float v5 = __ldcg(&src[p5.x]);
                float v6 = __ldcg(&src[p6.x]);
                float v7 = __ldcg(&src[p7.x]);
                acc += __int_as_float(p0.y) * v0 + __int_as_float(p1.y) * v1;
                acc += __int_as_float(p2.y) * v2 + __int_as_float(p3.y) * v3;
                acc += __int_as_float(p4.y) * v4 + __int_as_float(p5.y) * v5;
                acc += __int_as_float(p6.y) * v6 + __int_as_float(p7.y) * v7;
            }
            for (; i < elim; i++) {
                int2 p = sE[i];
                acc += __int_as_float(p.y) * __ldcg(&src[p.x]);
            }
            for (; i < e; i++) {
                int2 p = __ldg(&g_eL[s0 + i]);
                acc += __int_as_float(p.y) * __ldcg(&src[p.x]);
            }
        }

        float sq = 0.f;
        if (active) {
            float z = alpha * acc;
            float sg = (z > 0.f) ? 1.f : ((z < 0.f) ? -1.f : 0.f);
            y = z - TAU * sg;
            sq = y * y;
            __stcg(&dst[r], y);
        }
#pragma unroll
        for (int off = 16; off > 0; off >>= 1)
            sq += __shfl_down_sync(0xFFFFFFFFu, sq, off);
        if (lane == 0) wsum[wid] = sq;
        __syncthreads();
        if (wid == 0) {
            sq = (lane < (PWT >> 5)) ? wsum[lane] : 0.f;
#pragma unroll
            for (int off = 16; off > 0; off >>= 1)
                sq += __shfl_down_sync(0xFFFFFFFFu, sq, off);
            if (lane == 0)
                atomicAdd(&g_nleaf[(it * LEAFN + leaf) * 32], sq);
        }
        grid_sync_tree(&sense, it);
    }

    if (active) {
        float inv = 1.f / fmaxf(sqrtf(__ldcg(&g_norms[ITERS - 1])), 1e-12f);
        out[r] = y * inv;
    }
}

// ---------------------------------------------------------------------------
extern "C" void kernel_launch(void* const* d_in, const int* in_sizes, int n_in,
                              void* d_out, int out_size) {
    const int*   A_row = (const int*)d_in[0];
    const int*   A_col = (const int*)d_in[1];
    const float* A_val = (const float*)d_in[2];
    const int*   L_row = (const int*)d_in[3];
    const int*   L_col = (const int*)d_in[4];
    const float* L_val = (const float*)d_in[5];
    const float* embed = (const float*)d_in[6];
    const float* W1    = (const float*)d_in[7];
    const float* W2    = (const float*)d_in[8];
    const float* Ws    = (const float*)d_in[9];
    const int E = in_sizes[0];
    float* out = (float*)d_out;

    float *X, *X2, *ya;
    cudaGetSymbolAddress((void**)&X,  g_X);
    cudaGetSymbolAddress((void**)&X2, g_X2);
    cudaGetSymbolAddress((void**)&ya, g_ya);

    static int smem_set = 0;
    if (!smem_set) {
        cudaFuncSetAttribute(power_kernel,
                             cudaFuncAttributeMaxDynamicSharedMemorySize,
                             ECAP * (int)sizeof(int2));
        smem_set = 1;
    }

    csr_build_kernel<<<CB, CSRT>>>(A_row, A_col, A_val, L_row, L_col, L_val, E);

    const int LB = (NN * 16) / 512;   // 3125
    layer_kernel<<<LB, 512>>>(embed, X,  W1, Ws, ya, 0);
    layer_kernel<<<LB, 512>>>(X,     X2, W2, Ws, ya, 1);

    power_kernel<<<CB, PWT, ECAP * sizeof(int2)>>>(out);
}